// round 15
// baseline (speedup 1.0000x reference)
#include <cuda_runtime.h>
#include <cuda_fp16.h>
#include <mma.h>
#include <math.h>
#include <cstdint>

using namespace nvcuda;

#define HDIM   256
#define H3     768
#define MSGD   685
#define KPADM  704
#define UMAX   65536
#define NNMAX  200000

// -------- device scratch --------
__device__ __half g_gi[(size_t)UMAX * H3];
__device__ __half g_gh[(size_t)UMAX * H3];
__device__ __half g_m16[(size_t)UMAX * KPADM];
__device__ __half g_h16[(size_t)UMAX * HDIM];
__device__ __half g_w1[(size_t)H3 * KPADM];
__device__ __half g_w2[(size_t)H3 * HDIM];
__device__ int g_idx[UMAX];
__device__ int g_win[NNMAX];

__device__ __forceinline__ uint32_t smem_u32(const void* p) {
    uint32_t a;
    asm("{ .reg .u64 t; cvta.to.shared.u64 t, %1; cvt.u32.u64 %0, t; }" : "=r"(a) : "l"(p));
    return a;
}
__device__ __forceinline__ void cp16(uint32_t d, const void* s) {
    asm volatile("cp.async.cg.shared.global [%0], [%1], 16;" :: "r"(d), "l"(s));
}
#define CP_COMMIT() asm volatile("cp.async.commit_group;" ::: "memory")
#define CP_WAIT(n)  asm volatile("cp.async.wait_group %0;" :: "n"(n) : "memory")

// ============================ small kernels ============================
__global__ void cvt_idx_kernel(const unsigned* __restrict__ raw, int U, int nnodes) {
    bool is64 = (raw[1] == 0u && raw[3] == 0u && raw[5] == 0u && raw[7] == 0u);
    int u = blockIdx.x * blockDim.x + threadIdx.x;
    if (u < U) {
        int v = is64 ? (int)raw[2 * (size_t)u] : (int)raw[u];
        if (v < 0) v = 0;
        if (v >= nnodes) v = nnodes - 1;
        g_idx[u] = v;
    }
}
__global__ void init_win_kernel(int nnodes) {
    int i = blockIdx.x * blockDim.x + threadIdx.x;
    if (i < nnodes) g_win[i] = -1;
}
__global__ void vote_kernel(int U) {
    int u = blockIdx.x * blockDim.x + threadIdx.x;
    if (u < U) atomicMax(&g_win[g_idx[u]], u);
}
__global__ void copy_out_kernel(const float4* __restrict__ src,
                                float4* __restrict__ dst, long long n4) {
    long long i = (long long)blockIdx.x * blockDim.x + threadIdx.x;
    long long stride = (long long)gridDim.x * blockDim.x;
    for (; i < n4; i += stride) dst[i] = src[i];
}
__global__ void cast_pad_kernel(const float* __restrict__ src, __half* __restrict__ dst,
                                long long rows, int K, int Kpad) {
    long long total = rows * Kpad;
    long long i = (long long)blockIdx.x * blockDim.x + threadIdx.x;
    long long stride = (long long)gridDim.x * blockDim.x;
    for (; i < total; i += stride) {
        long long r = i / Kpad;
        int k = (int)(i - r * Kpad);
        dst[i] = __float2half_rn((k < K) ? __ldg(src + r * (long long)K + k) : 0.f);
    }
}
__global__ void gather_cast_kernel(const float* __restrict__ mem,
                                   __half* __restrict__ dst, long long total) {
    long long i = (long long)blockIdx.x * blockDim.x + threadIdx.x;
    long long stride = (long long)gridDim.x * blockDim.x;
    for (; i < total; i += stride) {
        int u = (int)(i >> 8);
        int c = (int)(i & 255);
        dst[i] = __float2half_rn(__ldg(mem + (size_t)g_idx[u] * HDIM + c));
    }
}

// ============================================================================
// C16[M,768] = A16[M,Kpad] @ W16[768,Kpad]^T  (fp16 in, fp32 accum, fp16 out)
// R12/R14-proven mainloop: CTA 128x128, 8 warps (4Mx2N) of 32x64, BK=32,
// double-buffered cp.async. Epilogue stages acc through smem, emits half.
#define LDS   40
#define MATB  10240
#define STGB  20480
__global__ __launch_bounds__(256)
void gemm_fp16(const __half* __restrict__ A16, const __half* __restrict__ W16,
               __half* __restrict__ C16, int M, int Kpad, int nchunks) {
    extern __shared__ char smem[];
    const uint32_t sb = smem_u32(smem);
    const int tid = threadIdx.x;
    const int wid = tid >> 5;
    const int m0 = blockIdx.y * 128;
    const int n0 = blockIdx.x * 128;
    const int wm = (wid & 3) * 32;
    const int wn = (wid >> 2) * 64;

    wmma::fragment<wmma::accumulator, 16, 16, 16, float> acc[2][4];
    #pragma unroll
    for (int i = 0; i < 2; i++)
        #pragma unroll
        for (int j = 0; j < 4; j++) wmma::fill_fragment(acc[i][j], 0.0f);

    auto issue = [&](int c, int s) {
        const int k0 = c * 32;
        const uint32_t base = sb + s * STGB;
        #pragma unroll
        for (int r = 0; r < 2; r++) {
            const int id  = tid + 256 * r;
            const int row = id >> 2;
            const int seg = id & 3;
            const uint32_t doff = row * (LDS * 2) + seg * 16;
            int gr = m0 + row; if (gr >= M) gr = M - 1;
            const size_t ga = (size_t)gr * Kpad + k0 + seg * 8;
            const size_t wa = (size_t)(n0 + row) * Kpad + k0 + seg * 8;
            cp16(base + doff,        A16 + ga);
            cp16(base + MATB + doff, W16 + wa);
        }
        CP_COMMIT();
    };

    issue(0, 0);
    for (int c = 0; c < nchunks; c++) {
        if (c + 1 < nchunks) { issue(c + 1, (c + 1) & 1); CP_WAIT(1); }
        else                 { CP_WAIT(0); }
        __syncthreads();

        const char* stg = smem + (c & 1) * STGB;
        const __half* Sa = (const __half*)(stg);
        const __half* Sw = (const __half*)(stg + MATB);

        #pragma unroll
        for (int ks = 0; ks < 2; ks++) {
            const int kk = ks * 16;
            wmma::fragment<wmma::matrix_a, 16, 16, 16, __half, wmma::row_major> a[2];
            wmma::fragment<wmma::matrix_b, 16, 16, 16, __half, wmma::col_major> b[4];
            #pragma unroll
            for (int i = 0; i < 2; i++)
                wmma::load_matrix_sync(a[i], Sa + (wm + i * 16) * LDS + kk, LDS);
            #pragma unroll
            for (int j = 0; j < 4; j++)
                wmma::load_matrix_sync(b[j], Sw + (wn + j * 16) * LDS + kk, LDS);
            #pragma unroll
            for (int i = 0; i < 2; i++)
                #pragma unroll
                for (int j = 0; j < 4; j++)
                    wmma::mma_sync(acc[i][j], a[i], b[j], acc[i][j]);
        }
        __syncthreads();
    }

    // ---- epilogue: two 64-row passes through smem (32 KB float staging) ----
    float* fstg = (float*)smem;
    #pragma unroll
    for (int hpass = 0; hpass < 2; hpass++) {
        __syncthreads();
        if ((wm >> 6) == hpass) {
            const int rbase = wm & 63;
            #pragma unroll
            for (int i = 0; i < 2; i++)
                #pragma unroll
                for (int j = 0; j < 4; j++)
                    wmma::store_matrix_sync(fstg + (rbase + i * 16) * 128 + wn + j * 16,
                                            acc[i][j], 128, wmma::mem_row_major);
        }
        __syncthreads();
        #pragma unroll
        for (int t = 0; t < 32; t++) {
            const int idx = tid + t * 256;       // 0..8191
            const int r  = idx >> 7;
            const int cc = idx & 127;
            const int row = m0 + hpass * 64 + r;
            if (row < M)
                C16[(size_t)row * H3 + n0 + cc] = __float2half_rn(fstg[idx]);
        }
    }
}

// ============================================================================
__global__ void gru_scatter_kernel(const float* __restrict__ mem,
                                   const float* __restrict__ b_ih,
                                   const float* __restrict__ b_hh,
                                   float* __restrict__ out, long long total) {
    long long i = (long long)blockIdx.x * blockDim.x + threadIdx.x;
    long long stride = (long long)gridDim.x * blockDim.x;
    for (; i < total; i += stride) {
        int u = (int)(i >> 8);
        int c = (int)(i & 255);
        int node = g_idx[u];
        if (g_win[node] != u) continue;

        const __half* gi = g_gi + (size_t)u * H3;
        const __half* gh = g_gh + (size_t)u * H3;
        float h = mem[(size_t)node * HDIM + c];

        float i_r = __half2float(gi[c])            + __ldg(b_ih + c);
        float i_z = __half2float(gi[HDIM + c])     + __ldg(b_ih + HDIM + c);
        float i_n = __half2float(gi[2 * HDIM + c]) + __ldg(b_ih + 2 * HDIM + c);
        float h_r = __half2float(gh[c])            + __ldg(b_hh + c);
        float h_z = __half2float(gh[HDIM + c])     + __ldg(b_hh + HDIM + c);
        float h_n = __half2float(gh[2 * HDIM + c]) + __ldg(b_hh + 2 * HDIM + c);

        float r = 1.f / (1.f + expf(-(i_r + h_r)));
        float z = 1.f / (1.f + expf(-(i_z + h_z)));
        float n = tanhf(i_n + r * h_n);
        out[(size_t)node * HDIM + c] = (1.f - z) * n + z * h;
    }
}

// ============================================================================
extern "C" void kernel_launch(void* const* d_in, const int* in_sizes, int n_in,
                              void* d_out, int out_size) {
    void *p;
    #define SYM(v, s) cudaGetSymbolAddress(&p, s); auto* v = decltype(&s[0])(p)
    SYM(d_gi,  g_gi);  SYM(d_gh,  g_gh);
    SYM(d_m16, g_m16); SYM(d_h16, g_h16);
    SYM(d_w1, g_w1);   SYM(d_w2, g_w2);
    #undef SYM

    const float *memory = nullptr, *messages = nullptr, *W_ih = nullptr,
                *W_hh = nullptr, *b_ih = nullptr, *b_hh = nullptr;
    const unsigned* node_raw = nullptr;
    for (int i = 0; i < n_in; i++) {
        long long s = in_sizes[i];
        const void* q = d_in[i];
        if (s == (long long)out_size)            memory   = (const float*)q;
        else if (s == (long long)H3 * MSGD)      W_ih     = (const float*)q;
        else if (s == (long long)H3 * HDIM)      W_hh     = (const float*)q;
        else if (s == H3) { if (!b_ih) b_ih = (const float*)q; else b_hh = (const float*)q; }
        else if (s == UMAX || s == 2 * UMAX)     node_raw = (const unsigned*)q;
        else if (s % MSGD == 0 && s > (long long)H3 * MSGD) messages = (const float*)q;
    }
    if (!memory)   memory   = (const float*)   d_in[0];
    if (!messages) messages = (const float*)   d_in[1];
    if (!node_raw) node_raw = (const unsigned*)d_in[2];
    if (!W_ih)     W_ih     = (const float*)   d_in[3];
    if (!W_hh)     W_hh     = (const float*)   d_in[4];
    if (!b_ih)     b_ih     = (const float*)   d_in[5];
    if (!b_hh)     b_hh     = (const float*)   d_in[6];

    const int nnodes = out_size / HDIM;
    int U = UMAX;
    for (int i = 0; i < n_in; i++)
        if (d_in[i] == (const void*)messages) { U = in_sizes[i] / MSGD; break; }

    static cudaStream_t s1 = nullptr, s2 = nullptr;
    static cudaEvent_t evIdx = nullptr, ev1 = nullptr, ev2 = nullptr;
    if (!s1) {
        cudaStreamCreateWithFlags(&s1, cudaStreamNonBlocking);
        cudaStreamCreateWithFlags(&s2, cudaStreamNonBlocking);
        cudaEventCreateWithFlags(&evIdx, cudaEventDisableTiming);
        cudaEventCreateWithFlags(&ev1,  cudaEventDisableTiming);
        cudaEventCreateWithFlags(&ev2,  cudaEventDisableTiming);
        cudaFuncSetAttribute(gemm_fp16, cudaFuncAttributeMaxDynamicSharedMemorySize, 2 * STGB);
    }

    float* out = (float*)d_out;

    // ---- 0: indices ----
    cvt_idx_kernel<<<(U + 255) / 256, 256>>>(node_raw, U, nnodes);
    cudaEventRecord(evIdx, 0);

    // ---- s1: copy_out + winner vote ----
    cudaStreamWaitEvent(s1, evIdx, 0);
    copy_out_kernel<<<2048, 256, 0, s1>>>((const float4*)memory, (float4*)out,
                                          (long long)out_size / 4);
    init_win_kernel<<<(nnodes + 255) / 256, 256, 0, s1>>>(nnodes);
    vote_kernel<<<(U + 255) / 256, 256, 0, s1>>>(U);
    cudaEventRecord(ev1, s1);

    // ---- s2: gather-cast h + W2 cast + GEMM2 (concurrent with 0) ----
    cudaStreamWaitEvent(s2, evIdx, 0);
    gather_cast_kernel<<<2048, 256, 0, s2>>>(memory, d_h16, (long long)U * HDIM);
    cast_pad_kernel<<<512, 256, 0, s2>>>(W_hh, d_w2, H3, HDIM, HDIM);
    {
        dim3 grid(H3 / 128, (U + 127) / 128);
        gemm_fp16<<<grid, 256, 2 * STGB, s2>>>(d_h16, d_w2, d_gh, U, HDIM, HDIM / 32);
    }
    cudaEventRecord(ev2, s2);

    // ---- 0: msgs cast + W1 cast + GEMM1 ----
    cast_pad_kernel<<<4096, 256>>>(messages, d_m16, U, MSGD, KPADM);
    cast_pad_kernel<<<512, 256>>>(W_ih, d_w1, H3, MSGD, KPADM);
    {
        dim3 grid(H3 / 128, (U + 127) / 128);
        gemm_fp16<<<grid, 256, 2 * STGB>>>(d_m16, d_w1, d_gi, U, KPADM, KPADM / 32);
    }

    // ---- 0: GRU (needs s1 + s2) ----
    cudaStreamWaitEvent(0, ev1, 0);
    cudaStreamWaitEvent(0, ev2, 0);
    gru_scatter_kernel<<<4096, 256>>>(memory, b_ih, b_hh, out, (long long)U * HDIM);
}

// round 16
// speedup vs baseline: 1.0350x; 1.0350x over previous
#include <cuda_runtime.h>
#include <cuda_fp16.h>
#include <mma.h>
#include <math.h>
#include <cstdint>

using namespace nvcuda;

#define HDIM   256
#define H3     768
#define MSGD   685
#define KPADM  704
#define UMAX   65536
#define NNMAX  200000

// -------- device scratch --------
__device__ __half g_gi[(size_t)UMAX * H3];
__device__ __half g_gh[(size_t)UMAX * H3];
__device__ __half g_m16[(size_t)UMAX * KPADM];
__device__ __half g_h16[(size_t)UMAX * HDIM];
__device__ __half g_w1[(size_t)H3 * KPADM];
__device__ __half g_w2[(size_t)H3 * HDIM];
__device__ int g_idx[UMAX];
__device__ int g_win[NNMAX];

__device__ __forceinline__ uint32_t smem_u32(const void* p) {
    uint32_t a;
    asm("{ .reg .u64 t; cvta.to.shared.u64 t, %1; cvt.u32.u64 %0, t; }" : "=r"(a) : "l"(p));
    return a;
}
__device__ __forceinline__ void cp16(uint32_t d, const void* s) {
    asm volatile("cp.async.cg.shared.global [%0], [%1], 16;" :: "r"(d), "l"(s));
}
#define CP_COMMIT() asm volatile("cp.async.commit_group;" ::: "memory")
#define CP_WAIT(n)  asm volatile("cp.async.wait_group %0;" :: "n"(n) : "memory")

// ============================ small kernels ============================
__global__ void cvt_idx_kernel(const unsigned* __restrict__ raw, int U, int nnodes) {
    bool is64 = (raw[1] == 0u && raw[3] == 0u && raw[5] == 0u && raw[7] == 0u);
    int u = blockIdx.x * blockDim.x + threadIdx.x;
    if (u < U) {
        int v = is64 ? (int)raw[2 * (size_t)u] : (int)raw[u];
        if (v < 0) v = 0;
        if (v >= nnodes) v = nnodes - 1;
        g_idx[u] = v;
    }
}
__global__ void init_win_kernel(int nnodes) {
    int i = blockIdx.x * blockDim.x + threadIdx.x;
    if (i < nnodes) g_win[i] = -1;
}
__global__ void vote_kernel(int U) {
    int u = blockIdx.x * blockDim.x + threadIdx.x;
    if (u < U) atomicMax(&g_win[g_idx[u]], u);
}
__global__ void copy_out_kernel(const float4* __restrict__ src,
                                float4* __restrict__ dst, long long n4) {
    long long i = (long long)blockIdx.x * blockDim.x + threadIdx.x;
    long long stride = (long long)gridDim.x * blockDim.x;
    for (; i < n4; i += stride) dst[i] = src[i];
}
__global__ void cast_pad_kernel(const float* __restrict__ src, __half* __restrict__ dst,
                                long long rows, int K, int Kpad) {
    long long total = rows * Kpad;
    long long i = (long long)blockIdx.x * blockDim.x + threadIdx.x;
    long long stride = (long long)gridDim.x * blockDim.x;
    for (; i < total; i += stride) {
        long long r = i / Kpad;
        int k = (int)(i - r * Kpad);
        dst[i] = __float2half_rn((k < K) ? __ldg(src + r * (long long)K + k) : 0.f);
    }
}
__global__ void gather_cast_kernel(const float* __restrict__ mem,
                                   __half* __restrict__ dst, long long total) {
    long long i = (long long)blockIdx.x * blockDim.x + threadIdx.x;
    long long stride = (long long)gridDim.x * blockDim.x;
    for (; i < total; i += stride) {
        int u = (int)(i >> 8);
        int c = (int)(i & 255);
        dst[i] = __float2half_rn(__ldg(mem + (size_t)g_idx[u] * HDIM + c));
    }
}

// ============================================================================
// C16[M,768] = A16[M,Kpad] @ W16[768,Kpad]^T  (fp16 in, fp32 accum, fp16 out)
// R12/R14-proven mainloop: CTA 128x128, 8 warps (4Mx2N) of 32x64, BK=32,
// double-buffered cp.async. Epilogue: direct half-fragment store (no staging).
#define LDS   40
#define MATB  10240
#define STGB  20480
__global__ __launch_bounds__(256)
void gemm_fp16(const __half* __restrict__ A16, const __half* __restrict__ W16,
               __half* __restrict__ C16, int M, int Kpad, int nchunks) {
    extern __shared__ char smem[];
    const uint32_t sb = smem_u32(smem);
    const int tid = threadIdx.x;
    const int wid = tid >> 5;
    const int m0 = blockIdx.y * 128;
    const int n0 = blockIdx.x * 128;
    const int wm = (wid & 3) * 32;
    const int wn = (wid >> 2) * 64;

    wmma::fragment<wmma::accumulator, 16, 16, 16, float> acc[2][4];
    #pragma unroll
    for (int i = 0; i < 2; i++)
        #pragma unroll
        for (int j = 0; j < 4; j++) wmma::fill_fragment(acc[i][j], 0.0f);

    auto issue = [&](int c, int s) {
        const int k0 = c * 32;
        const uint32_t base = sb + s * STGB;
        #pragma unroll
        for (int r = 0; r < 2; r++) {
            const int id  = tid + 256 * r;
            const int row = id >> 2;
            const int seg = id & 3;
            const uint32_t doff = row * (LDS * 2) + seg * 16;
            int gr = m0 + row; if (gr >= M) gr = M - 1;
            const size_t ga = (size_t)gr * Kpad + k0 + seg * 8;
            const size_t wa = (size_t)(n0 + row) * Kpad + k0 + seg * 8;
            cp16(base + doff,        A16 + ga);
            cp16(base + MATB + doff, W16 + wa);
        }
        CP_COMMIT();
    };

    issue(0, 0);
    for (int c = 0; c < nchunks; c++) {
        if (c + 1 < nchunks) { issue(c + 1, (c + 1) & 1); CP_WAIT(1); }
        else                 { CP_WAIT(0); }
        __syncthreads();

        const char* stg = smem + (c & 1) * STGB;
        const __half* Sa = (const __half*)(stg);
        const __half* Sw = (const __half*)(stg + MATB);

        #pragma unroll
        for (int ks = 0; ks < 2; ks++) {
            const int kk = ks * 16;
            wmma::fragment<wmma::matrix_a, 16, 16, 16, __half, wmma::row_major> a[2];
            wmma::fragment<wmma::matrix_b, 16, 16, 16, __half, wmma::col_major> b[4];
            #pragma unroll
            for (int i = 0; i < 2; i++)
                wmma::load_matrix_sync(a[i], Sa + (wm + i * 16) * LDS + kk, LDS);
            #pragma unroll
            for (int j = 0; j < 4; j++)
                wmma::load_matrix_sync(b[j], Sw + (wn + j * 16) * LDS + kk, LDS);
            #pragma unroll
            for (int i = 0; i < 2; i++)
                #pragma unroll
                for (int j = 0; j < 4; j++)
                    wmma::mma_sync(acc[i][j], a[i], b[j], acc[i][j]);
        }
        __syncthreads();
    }

    // ---- epilogue: convert acc frags to half frags, store directly ----
    #pragma unroll
    for (int i = 0; i < 2; i++) {
        int row = m0 + wm + i * 16;
        if (row + 16 > M) continue;
        #pragma unroll
        for (int j = 0; j < 4; j++) {
            wmma::fragment<wmma::accumulator, 16, 16, 16, __half> hacc;
            #pragma unroll
            for (int e = 0; e < hacc.num_elements; e++)
                hacc.x[e] = __float2half_rn(acc[i][j].x[e]);
            wmma::store_matrix_sync(C16 + (size_t)row * H3 + n0 + wn + j * 16,
                                    hacc, H3, wmma::mem_row_major);
        }
    }
}

// ============================================================================
__global__ void gru_scatter_kernel(const float* __restrict__ mem,
                                   const float* __restrict__ b_ih,
                                   const float* __restrict__ b_hh,
                                   float* __restrict__ out, long long total) {
    long long i = (long long)blockIdx.x * blockDim.x + threadIdx.x;
    long long stride = (long long)gridDim.x * blockDim.x;
    for (; i < total; i += stride) {
        int u = (int)(i >> 8);
        int c = (int)(i & 255);
        int node = g_idx[u];
        if (g_win[node] != u) continue;

        const __half* gi = g_gi + (size_t)u * H3;
        const __half* gh = g_gh + (size_t)u * H3;
        float h = mem[(size_t)node * HDIM + c];

        float i_r = __half2float(gi[c])            + __ldg(b_ih + c);
        float i_z = __half2float(gi[HDIM + c])     + __ldg(b_ih + HDIM + c);
        float i_n = __half2float(gi[2 * HDIM + c]) + __ldg(b_ih + 2 * HDIM + c);
        float h_r = __half2float(gh[c])            + __ldg(b_hh + c);
        float h_z = __half2float(gh[HDIM + c])     + __ldg(b_hh + HDIM + c);
        float h_n = __half2float(gh[2 * HDIM + c]) + __ldg(b_hh + 2 * HDIM + c);

        float r = 1.f / (1.f + expf(-(i_r + h_r)));
        float z = 1.f / (1.f + expf(-(i_z + h_z)));
        float n = tanhf(i_n + r * h_n);
        out[(size_t)node * HDIM + c] = (1.f - z) * n + z * h;
    }
}

// ============================================================================
extern "C" void kernel_launch(void* const* d_in, const int* in_sizes, int n_in,
                              void* d_out, int out_size) {
    void *p;
    #define SYM(v, s) cudaGetSymbolAddress(&p, s); auto* v = decltype(&s[0])(p)
    SYM(d_gi,  g_gi);  SYM(d_gh,  g_gh);
    SYM(d_m16, g_m16); SYM(d_h16, g_h16);
    SYM(d_w1, g_w1);   SYM(d_w2, g_w2);
    #undef SYM

    const float *memory = nullptr, *messages = nullptr, *W_ih = nullptr,
                *W_hh = nullptr, *b_ih = nullptr, *b_hh = nullptr;
    const unsigned* node_raw = nullptr;
    for (int i = 0; i < n_in; i++) {
        long long s = in_sizes[i];
        const void* q = d_in[i];
        if (s == (long long)out_size)            memory   = (const float*)q;
        else if (s == (long long)H3 * MSGD)      W_ih     = (const float*)q;
        else if (s == (long long)H3 * HDIM)      W_hh     = (const float*)q;
        else if (s == H3) { if (!b_ih) b_ih = (const float*)q; else b_hh = (const float*)q; }
        else if (s == UMAX || s == 2 * UMAX)     node_raw = (const unsigned*)q;
        else if (s % MSGD == 0 && s > (long long)H3 * MSGD) messages = (const float*)q;
    }
    if (!memory)   memory   = (const float*)   d_in[0];
    if (!messages) messages = (const float*)   d_in[1];
    if (!node_raw) node_raw = (const unsigned*)d_in[2];
    if (!W_ih)     W_ih     = (const float*)   d_in[3];
    if (!W_hh)     W_hh     = (const float*)   d_in[4];
    if (!b_ih)     b_ih     = (const float*)   d_in[5];
    if (!b_hh)     b_hh     = (const float*)   d_in[6];

    const int nnodes = out_size / HDIM;
    int U = UMAX;
    for (int i = 0; i < n_in; i++)
        if (d_in[i] == (const void*)messages) { U = in_sizes[i] / MSGD; break; }

    static cudaStream_t s1 = nullptr, s2 = nullptr;
    static cudaEvent_t evIdx = nullptr, ev1 = nullptr, ev2 = nullptr;
    if (!s1) {
        cudaStreamCreateWithFlags(&s1, cudaStreamNonBlocking);
        cudaStreamCreateWithFlags(&s2, cudaStreamNonBlocking);
        cudaEventCreateWithFlags(&evIdx, cudaEventDisableTiming);
        cudaEventCreateWithFlags(&ev1,  cudaEventDisableTiming);
        cudaEventCreateWithFlags(&ev2,  cudaEventDisableTiming);
        cudaFuncSetAttribute(gemm_fp16, cudaFuncAttributeMaxDynamicSharedMemorySize, 2 * STGB);
    }

    float* out = (float*)d_out;

    // ---- 0: indices ----
    cvt_idx_kernel<<<(U + 255) / 256, 256>>>(node_raw, U, nnodes);
    cudaEventRecord(evIdx, 0);

    // ---- s1: copy_out + winner vote ----
    cudaStreamWaitEvent(s1, evIdx, 0);
    copy_out_kernel<<<2048, 256, 0, s1>>>((const float4*)memory, (float4*)out,
                                          (long long)out_size / 4);
    init_win_kernel<<<(nnodes + 255) / 256, 256, 0, s1>>>(nnodes);
    vote_kernel<<<(U + 255) / 256, 256, 0, s1>>>(U);
    cudaEventRecord(ev1, s1);

    // ---- s2: gather-cast h + W2 cast + GEMM2 (concurrent with 0) ----
    cudaStreamWaitEvent(s2, evIdx, 0);
    gather_cast_kernel<<<2048, 256, 0, s2>>>(memory, d_h16, (long long)U * HDIM);
    cast_pad_kernel<<<512, 256, 0, s2>>>(W_hh, d_w2, H3, HDIM, HDIM);
    {
        dim3 grid(H3 / 128, (U + 127) / 128);
        gemm_fp16<<<grid, 256, 2 * STGB, s2>>>(d_h16, d_w2, d_gh, U, HDIM, HDIM / 32);
    }
    cudaEventRecord(ev2, s2);

    // ---- 0: msgs cast + W1 cast + GEMM1 ----
    cast_pad_kernel<<<4096, 256>>>(messages, d_m16, U, MSGD, KPADM);
    cast_pad_kernel<<<512, 256>>>(W_ih, d_w1, H3, MSGD, KPADM);
    {
        dim3 grid(H3 / 128, (U + 127) / 128);
        gemm_fp16<<<grid, 256, 2 * STGB>>>(d_m16, d_w1, d_gi, U, KPADM, KPADM / 32);
    }

    // ---- 0: GRU (needs s1 + s2) ----
    cudaStreamWaitEvent(0, ev1, 0);
    cudaStreamWaitEvent(0, ev2, 0);
    gru_scatter_kernel<<<4096, 256>>>(memory, b_ih, b_hh, out, (long long)U * HDIM);
}

// round 17
// speedup vs baseline: 1.0393x; 1.0042x over previous
#include <cuda_runtime.h>
#include <cuda_fp16.h>
#include <mma.h>
#include <math.h>
#include <cstdint>

using namespace nvcuda;

#define HDIM   256
#define H3     768
#define MSGD   685
#define KPADM  704
#define UMAX   65536
#define NNMAX  200000

// -------- device scratch --------
__device__ __half g_gi[(size_t)UMAX * H3];
__device__ __half g_gh[(size_t)UMAX * H3];
__device__ __half g_m16[(size_t)UMAX * KPADM];
__device__ __half g_h16[(size_t)UMAX * HDIM];
__device__ __half g_w1[(size_t)H3 * KPADM];
__device__ __half g_w2[(size_t)H3 * HDIM];
__device__ int g_idx[UMAX];
__device__ int g_win[NNMAX];

__device__ __forceinline__ uint32_t smem_u32(const void* p) {
    uint32_t a;
    asm("{ .reg .u64 t; cvta.to.shared.u64 t, %1; cvt.u32.u64 %0, t; }" : "=r"(a) : "l"(p));
    return a;
}
__device__ __forceinline__ void cp16(uint32_t d, const void* s) {
    asm volatile("cp.async.cg.shared.global [%0], [%1], 16;" :: "r"(d), "l"(s));
}
#define CP_COMMIT() asm volatile("cp.async.commit_group;" ::: "memory")
#define CP_WAIT(n)  asm volatile("cp.async.wait_group %0;" :: "n"(n) : "memory")

__device__ __forceinline__ float tanh_fast(float x) {
    float y;
    asm("tanh.approx.f32 %0, %1;" : "=f"(y) : "f"(x));
    return y;
}
__device__ __forceinline__ float sigmoid_fast(float x) {
    return fmaf(tanh_fast(0.5f * x), 0.5f, 0.5f);
}

// ============================ small kernels ============================
__global__ void cvt_idx_kernel(const unsigned* __restrict__ raw, int U, int nnodes) {
    bool is64 = (raw[1] == 0u && raw[3] == 0u && raw[5] == 0u && raw[7] == 0u);
    int u = blockIdx.x * blockDim.x + threadIdx.x;
    if (u < U) {
        int v = is64 ? (int)raw[2 * (size_t)u] : (int)raw[u];
        if (v < 0) v = 0;
        if (v >= nnodes) v = nnodes - 1;
        g_idx[u] = v;
    }
}
__global__ void init_win_kernel(int nnodes) {
    int i = blockIdx.x * blockDim.x + threadIdx.x;
    if (i < nnodes) g_win[i] = -1;
}
__global__ void vote_kernel(int U) {
    int u = blockIdx.x * blockDim.x + threadIdx.x;
    if (u < U) atomicMax(&g_win[g_idx[u]], u);
}
__global__ void copy_out_kernel(const float4* __restrict__ src,
                                float4* __restrict__ dst, long long n4) {
    long long i = (long long)blockIdx.x * blockDim.x + threadIdx.x;
    long long stride = (long long)gridDim.x * blockDim.x;
    for (; i < n4; i += stride) dst[i] = src[i];
}
__global__ void cast_pad_kernel(const float* __restrict__ src, __half* __restrict__ dst,
                                long long rows, int K, int Kpad) {
    long long total = rows * Kpad;
    long long i = (long long)blockIdx.x * blockDim.x + threadIdx.x;
    long long stride = (long long)gridDim.x * blockDim.x;
    for (; i < total; i += stride) {
        long long r = i / Kpad;
        int k = (int)(i - r * Kpad);
        dst[i] = __float2half_rn((k < K) ? __ldg(src + r * (long long)K + k) : 0.f);
    }
}
__global__ void gather_cast_kernel(const float* __restrict__ mem,
                                   __half* __restrict__ dst, long long total) {
    long long i = (long long)blockIdx.x * blockDim.x + threadIdx.x;
    long long stride = (long long)gridDim.x * blockDim.x;
    for (; i < total; i += stride) {
        int u = (int)(i >> 8);
        int c = (int)(i & 255);
        dst[i] = __float2half_rn(__ldg(mem + (size_t)g_idx[u] * HDIM + c));
    }
}

// ============================================================================
// C16[M,768] = A16[M,Kpad] @ W16[768,Kpad]^T  (fp16 in, fp32 accum, fp16 out)
// Proven mainloop: CTA 128x128, 8 warps (4Mx2N) of 32x64, BK=32,
// double-buffered cp.async. Epilogue: direct half-fragment store.
#define LDS   40
#define MATB  10240
#define STGB  20480
__global__ __launch_bounds__(256)
void gemm_fp16(const __half* __restrict__ A16, const __half* __restrict__ W16,
               __half* __restrict__ C16, int M, int Kpad, int nchunks) {
    extern __shared__ char smem[];
    const uint32_t sb = smem_u32(smem);
    const int tid = threadIdx.x;
    const int wid = tid >> 5;
    const int m0 = blockIdx.y * 128;
    const int n0 = blockIdx.x * 128;
    const int wm = (wid & 3) * 32;
    const int wn = (wid >> 2) * 64;

    wmma::fragment<wmma::accumulator, 16, 16, 16, float> acc[2][4];
    #pragma unroll
    for (int i = 0; i < 2; i++)
        #pragma unroll
        for (int j = 0; j < 4; j++) wmma::fill_fragment(acc[i][j], 0.0f);

    auto issue = [&](int c, int s) {
        const int k0 = c * 32;
        const uint32_t base = sb + s * STGB;
        #pragma unroll
        for (int r = 0; r < 2; r++) {
            const int id  = tid + 256 * r;
            const int row = id >> 2;
            const int seg = id & 3;
            const uint32_t doff = row * (LDS * 2) + seg * 16;
            int gr = m0 + row; if (gr >= M) gr = M - 1;
            const size_t ga = (size_t)gr * Kpad + k0 + seg * 8;
            const size_t wa = (size_t)(n0 + row) * Kpad + k0 + seg * 8;
            cp16(base + doff,        A16 + ga);
            cp16(base + MATB + doff, W16 + wa);
        }
        CP_COMMIT();
    };

    issue(0, 0);
    for (int c = 0; c < nchunks; c++) {
        if (c + 1 < nchunks) { issue(c + 1, (c + 1) & 1); CP_WAIT(1); }
        else                 { CP_WAIT(0); }
        __syncthreads();

        const char* stg = smem + (c & 1) * STGB;
        const __half* Sa = (const __half*)(stg);
        const __half* Sw = (const __half*)(stg + MATB);

        #pragma unroll
        for (int ks = 0; ks < 2; ks++) {
            const int kk = ks * 16;
            wmma::fragment<wmma::matrix_a, 16, 16, 16, __half, wmma::row_major> a[2];
            wmma::fragment<wmma::matrix_b, 16, 16, 16, __half, wmma::col_major> b[4];
            #pragma unroll
            for (int i = 0; i < 2; i++)
                wmma::load_matrix_sync(a[i], Sa + (wm + i * 16) * LDS + kk, LDS);
            #pragma unroll
            for (int j = 0; j < 4; j++)
                wmma::load_matrix_sync(b[j], Sw + (wn + j * 16) * LDS + kk, LDS);
            #pragma unroll
            for (int i = 0; i < 2; i++)
                #pragma unroll
                for (int j = 0; j < 4; j++)
                    wmma::mma_sync(acc[i][j], a[i], b[j], acc[i][j]);
        }
        __syncthreads();
    }

    #pragma unroll
    for (int i = 0; i < 2; i++) {
        int row = m0 + wm + i * 16;
        if (row + 16 > M) continue;
        #pragma unroll
        for (int j = 0; j < 4; j++) {
            wmma::fragment<wmma::accumulator, 16, 16, 16, __half> hacc;
            #pragma unroll
            for (int e = 0; e < hacc.num_elements; e++)
                hacc.x[e] = __float2half_rn(acc[i][j].x[e]);
            wmma::store_matrix_sync(C16 + (size_t)row * H3 + n0 + wn + j * 16,
                                    hacc, H3, wmma::mem_row_major);
        }
    }
}

// ============================================================================
// GRU: all nonlinearities via single-MUFU tanh.approx (sigmoid via identity).
__global__ void gru_scatter_kernel(const float* __restrict__ mem,
                                   const float* __restrict__ b_ih,
                                   const float* __restrict__ b_hh,
                                   float* __restrict__ out, long long total) {
    long long i = (long long)blockIdx.x * blockDim.x + threadIdx.x;
    long long stride = (long long)gridDim.x * blockDim.x;
    for (; i < total; i += stride) {
        int u = (int)(i >> 8);
        int c = (int)(i & 255);
        int node = g_idx[u];
        if (g_win[node] != u) continue;

        const __half* gi = g_gi + (size_t)u * H3;
        const __half* gh = g_gh + (size_t)u * H3;
        float h = mem[(size_t)node * HDIM + c];

        float i_r = __half2float(gi[c])            + __ldg(b_ih + c);
        float i_z = __half2float(gi[HDIM + c])     + __ldg(b_ih + HDIM + c);
        float i_n = __half2float(gi[2 * HDIM + c]) + __ldg(b_ih + 2 * HDIM + c);
        float h_r = __half2float(gh[c])            + __ldg(b_hh + c);
        float h_z = __half2float(gh[HDIM + c])     + __ldg(b_hh + HDIM + c);
        float h_n = __half2float(gh[2 * HDIM + c]) + __ldg(b_hh + 2 * HDIM + c);

        float r = sigmoid_fast(i_r + h_r);
        float z = sigmoid_fast(i_z + h_z);
        float n = tanh_fast(i_n + r * h_n);
        out[(size_t)node * HDIM + c] = (1.f - z) * n + z * h;
    }
}

// ============================================================================
extern "C" void kernel_launch(void* const* d_in, const int* in_sizes, int n_in,
                              void* d_out, int out_size) {
    void *p;
    #define SYM(v, s) cudaGetSymbolAddress(&p, s); auto* v = decltype(&s[0])(p)
    SYM(d_gi,  g_gi);  SYM(d_gh,  g_gh);
    SYM(d_m16, g_m16); SYM(d_h16, g_h16);
    SYM(d_w1, g_w1);   SYM(d_w2, g_w2);
    #undef SYM

    const float *memory = nullptr, *messages = nullptr, *W_ih = nullptr,
                *W_hh = nullptr, *b_ih = nullptr, *b_hh = nullptr;
    const unsigned* node_raw = nullptr;
    for (int i = 0; i < n_in; i++) {
        long long s = in_sizes[i];
        const void* q = d_in[i];
        if (s == (long long)out_size)            memory   = (const float*)q;
        else if (s == (long long)H3 * MSGD)      W_ih     = (const float*)q;
        else if (s == (long long)H3 * HDIM)      W_hh     = (const float*)q;
        else if (s == H3) { if (!b_ih) b_ih = (const float*)q; else b_hh = (const float*)q; }
        else if (s == UMAX || s == 2 * UMAX)     node_raw = (const unsigned*)q;
        else if (s % MSGD == 0 && s > (long long)H3 * MSGD) messages = (const float*)q;
    }
    if (!memory)   memory   = (const float*)   d_in[0];
    if (!messages) messages = (const float*)   d_in[1];
    if (!node_raw) node_raw = (const unsigned*)d_in[2];
    if (!W_ih)     W_ih     = (const float*)   d_in[3];
    if (!W_hh)     W_hh     = (const float*)   d_in[4];
    if (!b_ih)     b_ih     = (const float*)   d_in[5];
    if (!b_hh)     b_hh     = (const float*)   d_in[6];

    const int nnodes = out_size / HDIM;
    int U = UMAX;
    for (int i = 0; i < n_in; i++)
        if (d_in[i] == (const void*)messages) { U = in_sizes[i] / MSGD; break; }

    static cudaStream_t s1 = nullptr, s2 = nullptr;
    static cudaEvent_t evIdx = nullptr, ev1 = nullptr, ev2 = nullptr;
    if (!s1) {
        cudaStreamCreateWithFlags(&s1, cudaStreamNonBlocking);
        cudaStreamCreateWithFlags(&s2, cudaStreamNonBlocking);
        cudaEventCreateWithFlags(&evIdx, cudaEventDisableTiming);
        cudaEventCreateWithFlags(&ev1,  cudaEventDisableTiming);
        cudaEventCreateWithFlags(&ev2,  cudaEventDisableTiming);
        cudaFuncSetAttribute(gemm_fp16, cudaFuncAttributeMaxDynamicSharedMemorySize, 2 * STGB);
    }

    float* out = (float*)d_out;

    // ---- 0: indices ----
    cvt_idx_kernel<<<(U + 255) / 256, 256>>>(node_raw, U, nnodes);
    cudaEventRecord(evIdx, 0);

    // ---- s1: copy_out + winner vote ----
    cudaStreamWaitEvent(s1, evIdx, 0);
    copy_out_kernel<<<2048, 256, 0, s1>>>((const float4*)memory, (float4*)out,
                                          (long long)out_size / 4);
    init_win_kernel<<<(nnodes + 255) / 256, 256, 0, s1>>>(nnodes);
    vote_kernel<<<(U + 255) / 256, 256, 0, s1>>>(U);
    cudaEventRecord(ev1, s1);

    // ---- s2: gather-cast h + W2 cast + GEMM2 (concurrent with 0) ----
    cudaStreamWaitEvent(s2, evIdx, 0);
    gather_cast_kernel<<<2048, 256, 0, s2>>>(memory, d_h16, (long long)U * HDIM);
    cast_pad_kernel<<<512, 256, 0, s2>>>(W_hh, d_w2, H3, HDIM, HDIM);
    {
        dim3 grid(H3 / 128, (U + 127) / 128);
        gemm_fp16<<<grid, 256, 2 * STGB, s2>>>(d_h16, d_w2, d_gh, U, HDIM, HDIM / 32);
    }
    cudaEventRecord(ev2, s2);

    // ---- 0: msgs cast + W1 cast + GEMM1 ----
    cast_pad_kernel<<<4096, 256>>>(messages, d_m16, U, MSGD, KPADM);
    cast_pad_kernel<<<512, 256>>>(W_ih, d_w1, H3, MSGD, KPADM);
    {
        dim3 grid(H3 / 128, (U + 127) / 128);
        gemm_fp16<<<grid, 256, 2 * STGB>>>(d_m16, d_w1, d_gi, U, KPADM, KPADM / 32);
    }

    // ---- 0: GRU (needs s1 + s2) ----
    cudaStreamWaitEvent(0, ev1, 0);
    cudaStreamWaitEvent(0, ev2, 0);
    gru_scatter_kernel<<<4096, 256>>>(memory, b_ih, b_hh, out, (long long)U * HDIM);
}